// round 14
// baseline (speedup 1.0000x reference)
#include <cuda_runtime.h>
#include <cuda_fp16.h>
#include <cstdint>

// ---------------- problem constants ----------------
#define IN_CH   256
#define BATCH   8
#define KF      2304            // 9*256
#define NOUT    512
#define L2D     1024
#define MROWS   (BATCH * L2D)   // 8192
#define NCHK    (KF / 64)       // 36 k-chunks of 64 (64 fp16 = 128B row)

// GEMM tiling: CTA 128(M) x 128(N), 8 warps (2m x 4n) of 64x32, 2 CTAs/SM
#define NS   3                  // cp.async pipeline stages
#define TSZA (128 * 128)        // 16KB
#define TSZB (128 * 128)        // 16KB
#define STAGE (TSZA + TSZB)     // 32KB
#define SMEM_TOTAL (NS * STAGE) // 96KB -> 2 CTAs per SM

// scratch (__device__ globals: allocation-free rule)
__device__ __align__(16) __half g_A16[(size_t)MROWS * KF];
__device__ __align__(16) __half g_B16[(size_t)NOUT * KF];

// ---------------- helpers ----------------
__device__ __forceinline__ uint32_t h2u(__half2 h) {
    uint32_t u;
    __builtin_memcpy(&u, &h, 4);
    return u;
}
__device__ __forceinline__ void cpa16(uint32_t dst, const void* src) {
    asm volatile("cp.async.cg.shared.global [%0], [%1], 16;" :: "r"(dst), "l"(src));
}
#define CP_COMMIT() asm volatile("cp.async.commit_group;" ::: "memory")
#define CP_WAITN()  asm volatile("cp.async.wait_group %0;" :: "n"(NS - 2) : "memory")

__device__ __forceinline__ void ldm4(uint32_t* r, uint32_t addr) {
    asm volatile("ldmatrix.sync.aligned.m8n8.x4.shared.b16 {%0,%1,%2,%3}, [%4];"
                 : "=r"(r[0]), "=r"(r[1]), "=r"(r[2]), "=r"(r[3]) : "r"(addr));
}
__device__ __forceinline__ void mma16f(float* c, const uint32_t* a, const uint32_t* b) {
    asm volatile(
        "mma.sync.aligned.m16n8k16.row.col.f32.f16.f16.f32 "
        "{%0,%1,%2,%3}, {%4,%5,%6,%7}, {%8,%9}, {%0,%1,%2,%3};"
        : "+f"(c[0]), "+f"(c[1]), "+f"(c[2]), "+f"(c[3])
        : "r"(a[0]), "r"(a[1]), "r"(a[2]), "r"(a[3]), "r"(b[0]), "r"(b[1]));
}

// ---------------------------------------------------------------------------
// Kernel 1: im2col -> chunked fp16, 4 elems/thread, one 8B store.
// ---------------------------------------------------------------------------
__global__ void im2col_kernel(const float* __restrict__ x) {
    const int dd = blockIdx.x, ci = blockIdx.y, b = blockIdx.z;
    const int oy = dd / 3 - 1, ox = dd % 3 - 1;          // uniform per block
    const float* xp = x + (((size_t)(b * IN_CH + ci)) << 10);
    const uint32_t ibase = ((uint32_t)(b * KF + ci * 9 + dd)) << 10;
    const uint32_t r0 = ibase / KF, k0 = ibase % KF;     // uniform per block

    const int l = threadIdx.x << 2;                      // 0,4,...,1020
    const int h = l >> 5, w = l & 31;                    // w multiple of 4
    const int y = h + oy;
    const bool yok = (unsigned)y < 32u;
    const float* rowp = xp + (y << 5) + (w + ox);
    float v[4];
    #pragma unroll
    for (int e = 0; e < 4; e++) {
        int xw = w + ox + e;
        v[e] = (yok && (unsigned)xw < 32u) ? rowp[e] : 0.0f;
    }
    uint32_t k = k0 + (uint32_t)l, r = r0;
    if (k >= KF) { k -= KF; r++; }
    uint2 pk;
    pk.x = h2u(__floats2half2_rn(v[0], v[1]));
    pk.y = h2u(__floats2half2_rn(v[2], v[3]));
    *(uint2*)&g_A16[(((size_t)r * NCHK + (k >> 6)) << 6) + (k & 63)] = pk;
}

// ---------------------------------------------------------------------------
// Kernel 2: B^T expansion -> chunked fp16. BT[co][k] = w[p][q][(j-m)&63]
// ---------------------------------------------------------------------------
__global__ void beffT_kernel(const float* __restrict__ wgt) {
    const int co = blockIdx.y;
    const int k = blockIdx.x * 256 + threadIdx.x;
    const int q = k >> 6, m = k & 63;
    const int p = co >> 6, j = co & 63;
    float v = wgt[((p * 36 + q) << 6) + ((j - m) & 63)];
    g_B16[(((size_t)co * NCHK + (k >> 6)) << 6) + (k & 63)] = __float2half(v);
}

// ---------------------------------------------------------------------------
// Kernel 3: fp16 mma.sync GEMM, ldmatrix frags with A register double-buffer,
// 2 CTAs/SM. CTA 128x128, 8 warps (2m x 4n) of 64x32, 3-stage cp.async.
// ---------------------------------------------------------------------------
__global__ void __launch_bounds__(256, 2) gemm_kernel(float* __restrict__ out) {
    extern __shared__ char sm[];
    const uint32_t sbase = (uint32_t)__cvta_generic_to_shared(sm);
    const int tid = threadIdx.x;
    const int lane = tid & 31;
    const int wid = tid >> 5;
    const int g = lane >> 2, t = lane & 3;
    const int wm = wid >> 2, wn = wid & 3;       // 2m x 4n
    const int bm = blockIdx.y * 128;
    const int bn = blockIdx.x * 128;

    // ldmatrix per-lane base offsets (within a stage), ka=0
    uint32_t abase[4], bbase[2];
    {
        const int arow0 = wm * 64 + (lane & 7) + ((lane >> 3) & 1) * 8;
        const int ahi   = lane >> 4;
        #pragma unroll
        for (int ma = 0; ma < 4; ma++) {
            int row = arow0 + ma * 16;
            abase[ma] = (uint32_t)(row * 128 + ((ahi ^ (row & 7)) << 4));
        }
        const int brow0 = wn * 32 + (lane & 7) + (lane >> 4) * 8;
        const int bhi   = (lane >> 3) & 1;
        #pragma unroll
        for (int np = 0; np < 2; np++) {
            int row = brow0 + np * 16;
            bbase[np] = (uint32_t)(TSZA + row * 128 + ((bhi ^ (row & 7)) << 4));
        }
    }

    float acc[4][4][4];
    #pragma unroll
    for (int i = 0; i < 4; i++)
        #pragma unroll
        for (int j = 0; j < 4; j++)
            #pragma unroll
            for (int q = 0; q < 4; q++) acc[i][j][q] = 0.0f;

    auto load_chunk = [&](int c, int s) {
        char* As = sm + s * STAGE;
        char* Bs = As + TSZA;
        #pragma unroll
        for (int i = 0; i < 4; i++) {            // A & B: 128 rows x 8 x 16B each
            int id = tid + i * 256;
            int row = id >> 3, cj = id & 7;
            uint32_t swo = (uint32_t)(row * 128 + ((cj ^ (row & 7)) << 4));
            cpa16((uint32_t)__cvta_generic_to_shared(As + swo),
                  &g_A16[(((size_t)(bm + row) * NCHK + c) << 6) + (cj << 3)]);
            cpa16((uint32_t)__cvta_generic_to_shared(Bs + swo),
                  &g_B16[(((size_t)(bn + row) * NCHK + c) << 6) + (cj << 3)]);
        }
    };

    auto compute = [&](int s) {
        const uint32_t stg = sbase + (uint32_t)(s * STAGE);
        uint32_t a[2][4][4];                     // A frags, double-buffered over ka
        uint32_t bb[2][4];                       // B frags, current ka only
        #pragma unroll
        for (int ma = 0; ma < 4; ma++)           // preload A(ka=0)
            ldm4(a[0][ma], stg + abase[ma]);
        #pragma unroll
        for (int ka = 0; ka < 4; ka++) {
            const int cur = ka & 1, nxt = cur ^ 1;
            const uint32_t kx  = (uint32_t)(ka << 5);
            const uint32_t kxn = (uint32_t)((ka + 1) << 5);
            #pragma unroll
            for (int np = 0; np < 2; np++)       // B(ka): needed first
                ldm4(bb[np], stg + (bbase[np] ^ kx));
            if (ka < 3) {
                #pragma unroll
                for (int ma = 0; ma < 4; ma++)   // prefetch A(ka+1) into alt buf
                    ldm4(a[nxt][ma], stg + (abase[ma] ^ kxn));
            }
            #pragma unroll
            for (int ma = 0; ma < 4; ma++)
                #pragma unroll
                for (int na = 0; na < 4; na++)
                    mma16f(acc[ma][na], a[cur][ma], &bb[na >> 1][(na & 1) << 1]);
        }
    };

    // prologue: prefetch NS-1 chunks
    #pragma unroll
    for (int s = 0; s < NS - 1; s++) { load_chunk(s, s); CP_COMMIT(); }

    int sc = 0, sn = NS - 1;                     // compute / next-load stage ids
    for (int c = 0; c < NCHK; c++) {
        CP_WAITN();
        __syncthreads();
        const int cn = c + NS - 1;
        if (cn < NCHK) { load_chunk(cn, sn); CP_COMMIT(); }
        compute(sc);
        sc = (sc + 1 == NS) ? 0 : sc + 1;
        sn = (sn + 1 == NS) ? 0 : sn + 1;
    }

    // epilogue: C[r][co] -> out[b][co][l2], r = b*1024 + l2
    #pragma unroll
    for (int ma = 0; ma < 4; ma++) {
        #pragma unroll
        for (int half = 0; half < 2; half++) {
            const int r = bm + wm * 64 + ma * 16 + g + half * 8;
            const int b = r >> 10;
            const int l2 = r & (L2D - 1);
            float* op = out + (((size_t)b * NOUT) << 10) + l2;
            #pragma unroll
            for (int na = 0; na < 4; na++) {
                const int co = bn + wn * 32 + na * 8 + t * 2;
                op[(size_t)co << 10]       = acc[ma][na][half * 2 + 0];
                op[(size_t)(co + 1) << 10] = acc[ma][na][half * 2 + 1];
            }
        }
    }
}

// ---------------------------------------------------------------------------
extern "C" void kernel_launch(void* const* d_in, const int* in_sizes, int n_in,
                              void* d_out, int out_size) {
    const float* x = (const float*)d_in[0];
    const float* w = (const float*)d_in[1];
    if (n_in >= 2 && in_sizes[0] == 8 * 36 * 64) {   // defensive swap by size
        const float* tp = x; x = w; w = tp;
    }
    float* out = (float*)d_out;

    cudaFuncSetAttribute(gemm_kernel, cudaFuncAttributeMaxDynamicSharedMemorySize, SMEM_TOTAL);

    im2col_kernel<<<dim3(9, IN_CH, BATCH), 256>>>(x);
    beffT_kernel<<<dim3(KF / 256, NOUT), 256>>>(w);
    gemm_kernel<<<dim3(NOUT / 128, MROWS / 128), 256, SMEM_TOTAL>>>(out);
    (void)out_size;
}

// round 15
// speedup vs baseline: 1.0740x; 1.0740x over previous
#include <cuda_runtime.h>
#include <cuda_fp16.h>
#include <cstdint>

// ---------------- problem constants ----------------
#define IN_CH   256
#define BATCH   8
#define KF      2304            // 9*256
#define NOUT    512
#define L2D     1024
#define MROWS   (BATCH * L2D)   // 8192
#define NCHK    (KF / 64)       // 36 k-chunks of 64 (64 fp16 = 128B row)

// GEMM tiling: CTA 128(M) x 128(N), 8 warps (2m x 4n) of 64x32, 2 CTAs/SM
#define NS   3                  // cp.async pipeline stages
#define TSZA (128 * 128)        // 16KB
#define TSZB (128 * 128)        // 16KB
#define STAGE (TSZA + TSZB)     // 32KB
#define SMEM_TOTAL (NS * STAGE) // 96KB -> 2 CTAs per SM

// scratch (__device__ globals: allocation-free rule)
__device__ __align__(16) __half g_A16[(size_t)MROWS * KF];
__device__ __align__(16) __half g_B16[(size_t)NOUT * KF];

// ---------------- helpers ----------------
__device__ __forceinline__ uint32_t h2u(__half2 h) {
    uint32_t u;
    __builtin_memcpy(&u, &h, 4);
    return u;
}
__device__ __forceinline__ void cpa16(uint32_t dst, const void* src) {
    asm volatile("cp.async.cg.shared.global [%0], [%1], 16;" :: "r"(dst), "l"(src));
}
#define CP_COMMIT() asm volatile("cp.async.commit_group;" ::: "memory")
#define CP_WAITN()  asm volatile("cp.async.wait_group %0;" :: "n"(NS - 2) : "memory")

__device__ __forceinline__ void ldm4(uint32_t* r, uint32_t addr) {
    asm volatile("ldmatrix.sync.aligned.m8n8.x4.shared.b16 {%0,%1,%2,%3}, [%4];"
                 : "=r"(r[0]), "=r"(r[1]), "=r"(r[2]), "=r"(r[3]) : "r"(addr));
}
__device__ __forceinline__ void mma16f(float* c, const uint32_t* a, const uint32_t* b) {
    asm volatile(
        "mma.sync.aligned.m16n8k16.row.col.f32.f16.f16.f32 "
        "{%0,%1,%2,%3}, {%4,%5,%6,%7}, {%8,%9}, {%0,%1,%2,%3};"
        : "+f"(c[0]), "+f"(c[1]), "+f"(c[2]), "+f"(c[3])
        : "r"(a[0]), "r"(a[1]), "r"(a[2]), "r"(a[3]), "r"(b[0]), "r"(b[1]));
}

// ---------------------------------------------------------------------------
// Kernel 1: im2col, smem-staged. grid (IN_CH, BATCH), 256 thr.
// Load the 32x32 image ONCE (fp32->fp16 once), then emit the 9 shifted
// variants from smem. Thread owns pixel quad l = tid*4.
// ---------------------------------------------------------------------------
__global__ void im2col_kernel(const float* __restrict__ x) {
    __shared__ __half tile[L2D];
    const int ci = blockIdx.x, b = blockIdx.y;
    const int tid = threadIdx.x;

    const float4 v = ((const float4*)(x + (((size_t)(b * IN_CH + ci)) << 10)))[tid];
    ((__half2*)tile)[tid * 2 + 0] = __floats2half2_rn(v.x, v.y);
    ((__half2*)tile)[tid * 2 + 1] = __floats2half2_rn(v.z, v.w);
    __syncthreads();

    const int l = tid << 2;
    const int h = l >> 5, w = l & 31;
    const uint32_t base0 = ((uint32_t)(b * KF + ci * 9)) << 10;
    const __half hz = __float2half(0.0f);

    #pragma unroll
    for (int dd = 0; dd < 9; dd++) {
        const int oy = dd / 3 - 1, ox = dd % 3 - 1;      // compile-time consts
        const int y = h + oy;
        const bool yok = (unsigned)y < 32u;
        __half hv[4];
        #pragma unroll
        for (int e = 0; e < 4; e++) {
            const int xw = w + ox + e;
            hv[e] = (yok && (unsigned)xw < 32u) ? tile[(y << 5) + xw] : hz;
        }
        uint2 pk;
        pk.x = h2u(__halves2half2(hv[0], hv[1]));
        pk.y = h2u(__halves2half2(hv[2], hv[3]));
        const uint32_t ibase = base0 + ((uint32_t)dd << 10);
        uint32_t r = ibase / KF;
        uint32_t k = ibase - r * KF + (uint32_t)l;
        if (k >= KF) { k -= KF; r++; }
        *(uint2*)&g_A16[(((size_t)r * NCHK + (k >> 6)) << 6) + (k & 63)] = pk;
    }
}

// ---------------------------------------------------------------------------
// Kernel 2: B^T expansion -> chunked fp16. BT[co][k] = w[p][q][(j-m)&63]
// ---------------------------------------------------------------------------
__global__ void beffT_kernel(const float* __restrict__ wgt) {
    const int co = blockIdx.y;
    const int k = blockIdx.x * 256 + threadIdx.x;
    const int q = k >> 6, m = k & 63;
    const int p = co >> 6, j = co & 63;
    float v = wgt[((p * 36 + q) << 6) + ((j - m) & 63)];
    g_B16[(((size_t)co * NCHK + (k >> 6)) << 6) + (k & 63)] = __float2half(v);
}

// ---------------------------------------------------------------------------
// Kernel 3: fp16 mma.sync GEMM, ldmatrix frags, 2 CTAs/SM (R13 structure).
// CTA 128x128, 8 warps (2m x 4n) of 64x32, 3-stage cp.async.
// ---------------------------------------------------------------------------
__global__ void __launch_bounds__(256, 2) gemm_kernel(float* __restrict__ out) {
    extern __shared__ char sm[];
    const uint32_t sbase = (uint32_t)__cvta_generic_to_shared(sm);
    const int tid = threadIdx.x;
    const int lane = tid & 31;
    const int wid = tid >> 5;
    const int g = lane >> 2, t = lane & 3;
    const int wm = wid >> 2, wn = wid & 3;       // 2m x 4n
    const int bm = blockIdx.y * 128;
    const int bn = blockIdx.x * 128;

    // ldmatrix per-lane base offsets (within a stage), ka=0
    uint32_t abase[4], bbase[2];
    {
        const int arow0 = wm * 64 + (lane & 7) + ((lane >> 3) & 1) * 8;
        const int ahi   = lane >> 4;
        #pragma unroll
        for (int ma = 0; ma < 4; ma++) {
            int row = arow0 + ma * 16;
            abase[ma] = (uint32_t)(row * 128 + ((ahi ^ (row & 7)) << 4));
        }
        const int brow0 = wn * 32 + (lane & 7) + (lane >> 4) * 8;
        const int bhi   = (lane >> 3) & 1;
        #pragma unroll
        for (int np = 0; np < 2; np++) {
            int row = brow0 + np * 16;
            bbase[np] = (uint32_t)(TSZA + row * 128 + ((bhi ^ (row & 7)) << 4));
        }
    }

    float acc[4][4][4];
    #pragma unroll
    for (int i = 0; i < 4; i++)
        #pragma unroll
        for (int j = 0; j < 4; j++)
            #pragma unroll
            for (int q = 0; q < 4; q++) acc[i][j][q] = 0.0f;

    auto load_chunk = [&](int c, int s) {
        char* As = sm + s * STAGE;
        char* Bs = As + TSZA;
        #pragma unroll
        for (int i = 0; i < 4; i++) {            // A & B: 128 rows x 8 x 16B each
            int id = tid + i * 256;
            int row = id >> 3, cj = id & 7;
            uint32_t swo = (uint32_t)(row * 128 + ((cj ^ (row & 7)) << 4));
            cpa16((uint32_t)__cvta_generic_to_shared(As + swo),
                  &g_A16[(((size_t)(bm + row) * NCHK + c) << 6) + (cj << 3)]);
            cpa16((uint32_t)__cvta_generic_to_shared(Bs + swo),
                  &g_B16[(((size_t)(bn + row) * NCHK + c) << 6) + (cj << 3)]);
        }
    };

    auto compute = [&](int s) {
        const uint32_t stg = sbase + (uint32_t)(s * STAGE);
        #pragma unroll
        for (int ka = 0; ka < 4; ka++) {
            const uint32_t kx = (uint32_t)(ka << 5);
            uint32_t a[4][4], bb[2][4];
            #pragma unroll
            for (int ma = 0; ma < 4; ma++)
                ldm4(a[ma], stg + (abase[ma] ^ kx));
            #pragma unroll
            for (int np = 0; np < 2; np++)
                ldm4(bb[np], stg + (bbase[np] ^ kx));
            #pragma unroll
            for (int ma = 0; ma < 4; ma++)
                #pragma unroll
                for (int na = 0; na < 4; na++)
                    mma16f(acc[ma][na], a[ma], &bb[na >> 1][(na & 1) << 1]);
        }
    };

    // prologue: prefetch NS-1 chunks
    #pragma unroll
    for (int s = 0; s < NS - 1; s++) { load_chunk(s, s); CP_COMMIT(); }

    int sc = 0, sn = NS - 1;                     // compute / next-load stage ids
    for (int c = 0; c < NCHK; c++) {
        CP_WAITN();
        __syncthreads();
        const int cn = c + NS - 1;
        if (cn < NCHK) { load_chunk(cn, sn); CP_COMMIT(); }
        compute(sc);
        sc = (sc + 1 == NS) ? 0 : sc + 1;
        sn = (sn + 1 == NS) ? 0 : sn + 1;
    }

    // epilogue: C[r][co] -> out[b][co][l2], r = b*1024 + l2
    #pragma unroll
    for (int ma = 0; ma < 4; ma++) {
        #pragma unroll
        for (int half = 0; half < 2; half++) {
            const int r = bm + wm * 64 + ma * 16 + g + half * 8;
            const int b = r >> 10;
            const int l2 = r & (L2D - 1);
            float* op = out + (((size_t)b * NOUT) << 10) + l2;
            #pragma unroll
            for (int na = 0; na < 4; na++) {
                const int co = bn + wn * 32 + na * 8 + t * 2;
                op[(size_t)co << 10]       = acc[ma][na][half * 2 + 0];
                op[(size_t)(co + 1) << 10] = acc[ma][na][half * 2 + 1];
            }
        }
    }
}

// ---------------------------------------------------------------------------
extern "C" void kernel_launch(void* const* d_in, const int* in_sizes, int n_in,
                              void* d_out, int out_size) {
    const float* x = (const float*)d_in[0];
    const float* w = (const float*)d_in[1];
    if (n_in >= 2 && in_sizes[0] == 8 * 36 * 64) {   // defensive swap by size
        const float* tp = x; x = w; w = tp;
    }
    float* out = (float*)d_out;

    cudaFuncSetAttribute(gemm_kernel, cudaFuncAttributeMaxDynamicSharedMemorySize, SMEM_TOTAL);

    im2col_kernel<<<dim3(IN_CH, BATCH), 256>>>(x);
    beffT_kernel<<<dim3(KF / 256, NOUT), 256>>>(w);
    gemm_kernel<<<dim3(NOUT / 128, MROWS / 128), 256, SMEM_TOTAL>>>(out);
    (void)out_size;
}